// round 11
// baseline (speedup 1.0000x reference)
#include <cuda_runtime.h>
#include <math.h>

#define SCALE_F 0.125f
#define EPS_F 1e-5f

// scratch (float offsets)
#define O_XT   0
#define O_QT   16384
#define O_KT   32768
#define O_VT   49152
#define O_ATT  65536
#define O_TMP  81920
#define O_QC   98304
#define O_CATT 114688
#define O_HID  131072
#define O_U    196608
#define O_SC   458752
#define O_AT   720896
#define O_CT0  983040
#define O_CT1  1245184
__device__ float g_buf[1507328];

__global__ void tin(const float* __restrict__ x, float* __restrict__ XT) {
    int i = blockIdx.x * 256 + threadIdx.x;
    if (i < 16384) XT[(i & 1023) * 16 + (i >> 10)] = x[i];
}

// outT[o*16+b] = act(sum_k (A+A2)[(base+k)*16+b] * W[k*N+o] + bias[o]) (+resid)
__global__ void gemv16(const float* __restrict__ A, const float* __restrict__ A2,
                       const float* __restrict__ W, const float* __restrict__ bias,
                       const float* __restrict__ resid, float* __restrict__ outT,
                       int N, int K, int hs, int relu) {
    const int tid = threadIdx.x, ox = tid & 15, ks = tid >> 4;
    const int o = blockIdx.x * 16 + ox;
    const int klen = K >> 4, k0 = ks * klen;
    const int base = hs ? (o >> 6) * hs : 0;
    const float* Wp = W + (size_t)k0 * N + o;
    float acc[16];
#pragma unroll
    for (int b = 0; b < 16; b++) acc[b] = 0.f;
    for (int kk = 0; kk < klen; kk++) {
        float w = __ldg(Wp); Wp += N;
        const float4* a4 = (const float4*)(A + (size_t)(base + k0 + kk) * 16);
        float4 a0 = __ldg(a4), a1 = __ldg(a4 + 1), a2 = __ldg(a4 + 2), a3 = __ldg(a4 + 3);
        if (A2) {
            const float4* c4 = (const float4*)(A2 + (size_t)(base + k0 + kk) * 16);
            float4 c0 = __ldg(c4), c1 = __ldg(c4 + 1), c2 = __ldg(c4 + 2), c3 = __ldg(c4 + 3);
            a0.x += c0.x; a0.y += c0.y; a0.z += c0.z; a0.w += c0.w;
            a1.x += c1.x; a1.y += c1.y; a1.z += c1.z; a1.w += c1.w;
            a2.x += c2.x; a2.y += c2.y; a2.z += c2.z; a2.w += c2.w;
            a3.x += c3.x; a3.y += c3.y; a3.z += c3.z; a3.w += c3.w;
        }
        acc[0] += w * a0.x; acc[1] += w * a0.y; acc[2] += w * a0.z; acc[3] += w * a0.w;
        acc[4] += w * a1.x; acc[5] += w * a1.y; acc[6] += w * a1.z; acc[7] += w * a1.w;
        acc[8] += w * a2.x; acc[9] += w * a2.y; acc[10] += w * a2.z; acc[11] += w * a2.w;
        acc[12] += w * a3.x; acc[13] += w * a3.y; acc[14] += w * a3.z; acc[15] += w * a3.w;
    }
    __shared__ float sh[256][17];
#pragma unroll
    for (int b = 0; b < 16; b++) sh[tid][b] = acc[b];
    __syncthreads();
    const int oxr = tid >> 4, b = tid & 15;
    float s = 0.f;
#pragma unroll
    for (int q = 0; q < 16; q++) s += sh[q * 16 + oxr][b];
    const int oo = blockIdx.x * 16 + oxr;
    float v = s + bias[oo];
    if (relu) v = fmaxf(v, 0.f);
    if (resid) v += resid[oo * 16 + b];
    outT[oo * 16 + b] = v;
}

// one block per (b,h): scores over 1024 kv, softmax, weighted V sum
__global__ void self_attn(const float* __restrict__ QT, const float* __restrict__ KT,
                          const float* __restrict__ VT, const float* __restrict__ kc,
                          const float* __restrict__ vc, float* __restrict__ ATT) {
    const int b = blockIdx.x, h = blockIdx.y, tid = threadIdx.x;
    __shared__ float q[64], sc[1024], red[256], outp[4][64];
    if (tid < 64) q[tid] = QT[(h * 64 + tid) * 16 + b];
    __syncthreads();
    const size_t cbase = (size_t)(b * 16 + h) * 1023 * 64;
    for (int t = tid; t < 1024; t += 256) {
        float a = 0.f;
        if (t < 1023) {
            const float4* kp = (const float4*)(kc + cbase + (size_t)t * 64);
            const float4* qp = (const float4*)q;
#pragma unroll
            for (int i = 0; i < 16; i++) {
                float4 kv = __ldg(kp + i), qv = qp[i];
                a += kv.x * qv.x + kv.y * qv.y + kv.z * qv.z + kv.w * qv.w;
            }
        } else {
            for (int j = 0; j < 64; j++) a += q[j] * KT[(h * 64 + j) * 16 + b];
        }
        sc[t] = a * SCALE_F;
    }
    __syncthreads();
    float m = -1e30f;
    for (int t = tid; t < 1024; t += 256) m = fmaxf(m, sc[t]);
    red[tid] = m; __syncthreads();
    for (int s = 128; s > 0; s >>= 1) { if (tid < s) red[tid] = fmaxf(red[tid], red[tid + s]); __syncthreads(); }
    m = red[0]; __syncthreads();
    float ssum = 0.f;
    for (int t = tid; t < 1024; t += 256) { float e = __expf(sc[t] - m); sc[t] = e; ssum += e; }
    red[tid] = ssum; __syncthreads();
    for (int s = 128; s > 0; s >>= 1) { if (tid < s) red[tid] += red[tid + s]; __syncthreads(); }
    const float sum = red[0];
    __syncthreads();
    const int g = tid >> 6, j = tid & 63;
    float acc = 0.f;
    for (int t = g; t < 1024; t += 4) {
        float v = (t < 1023) ? __ldg(vc + cbase + (size_t)t * 64 + j) : VT[(h * 64 + j) * 16 + b];
        acc += sc[t] * v;
    }
    outp[g][j] = acc;
    __syncthreads();
    if (tid < 64)
        ATT[(h * 64 + tid) * 16 + b] = (outp[0][tid] + outp[1][tid] + outp[2][tid] + outp[3][tid]) / sum;
}

__global__ void lnk(const float* __restrict__ T, const float* __restrict__ g,
                    const float* __restrict__ be, float* __restrict__ XT) {
    const int b = blockIdx.x, tid = threadIdx.x;
    __shared__ float red[256];
    float s = 0.f;
    for (int o = tid; o < 1024; o += 256) s += T[o * 16 + b];
    red[tid] = s; __syncthreads();
    for (int st = 128; st > 0; st >>= 1) { if (tid < st) red[tid] += red[tid + st]; __syncthreads(); }
    const float mean = red[0] * (1.f / 1024.f);
    __syncthreads();
    float v = 0.f;
    for (int o = tid; o < 1024; o += 256) { float d = T[o * 16 + b] - mean; v += d * d; }
    red[tid] = v; __syncthreads();
    for (int st = 128; st > 0; st >>= 1) { if (tid < st) red[tid] += red[tid + st]; __syncthreads(); }
    const float rstd = rsqrtf(red[0] * (1.f / 1024.f) + EPS_F);
    for (int o = tid; o < 1024; o += 256)
        XT[o * 16 + b] = (T[o * 16 + b] - mean) * rstd * g[o] + be[o];
}

// U[(b*16+h)*1024+d] = sum_j Wk[d*1024 + h*64+j] * QC[(h*64+j)*16+b]
__global__ void ukern(const float* __restrict__ Wk, const float* __restrict__ QC,
                      float* __restrict__ U) {
    const int d = blockIdx.x, tid = threadIdx.x;
    __shared__ float w[1024];
    for (int i = tid; i < 1024; i += 256) w[i] = __ldg(&Wk[(size_t)d * 1024 + i]);
    __syncthreads();
    const int b = tid & 15, h = tid >> 4;
    float a = 0.f;
#pragma unroll 8
    for (int j = 0; j < 64; j++) a += w[h * 64 + j] * QC[(h * 64 + j) * 16 + b];
    U[(size_t)(b * 16 + h) * 1024 + d] = a;
}

// SC[(b*16+h)*1024+s] = enc[b,s,:] . U[b,h,:]
__global__ void xscores(const float* __restrict__ enc, const float* __restrict__ U,
                        float* __restrict__ SC) {
    const int b = blockIdx.x, s = blockIdx.y * 128 + threadIdx.x;
    __shared__ float ush[16][512];
    float acc[16];
#pragma unroll
    for (int h = 0; h < 16; h++) acc[h] = 0.f;
    const float* ep = enc + (size_t)(b * 1024 + s) * 1024;
    for (int half = 0; half < 2; half++) {
        __syncthreads();
        for (int i = threadIdx.x; i < 8192; i += 128)
            ush[i >> 9][i & 511] = __ldg(&U[(size_t)(b * 16 + (i >> 9)) * 1024 + half * 512 + (i & 511)]);
        __syncthreads();
        for (int d = 0; d < 512; d += 4) {
            float4 e = __ldg((const float4*)(ep + half * 512 + d));
#pragma unroll
            for (int h = 0; h < 16; h++) {
                float4 u4 = *(const float4*)&ush[h][d];
                acc[h] += e.x * u4.x + e.y * u4.y + e.z * u4.z + e.w * u4.w;
            }
        }
    }
#pragma unroll
    for (int h = 0; h < 16; h++) SC[(size_t)(b * 16 + h) * 1024 + s] = acc[h];
}

__global__ void xsoftmax(const float* __restrict__ SC, float* __restrict__ AT) {
    const int b = blockIdx.x, h = blockIdx.y, tid = threadIdx.x;
    const float* p = SC + (size_t)(b * 16 + h) * 1024;
    __shared__ float red[256];
    float v[4], m = -1e30f;
#pragma unroll
    for (int i = 0; i < 4; i++) { v[i] = SCALE_F * p[tid + i * 256]; m = fmaxf(m, v[i]); }
    red[tid] = m; __syncthreads();
    for (int st = 128; st > 0; st >>= 1) { if (tid < st) red[tid] = fmaxf(red[tid], red[tid + st]); __syncthreads(); }
    m = red[0]; __syncthreads();
    float ssum = 0.f;
#pragma unroll
    for (int i = 0; i < 4; i++) { v[i] = __expf(v[i] - m); ssum += v[i]; }
    red[tid] = ssum; __syncthreads();
    for (int st = 128; st > 0; st >>= 1) { if (tid < st) red[tid] += red[tid + st]; __syncthreads(); }
    const float inv = 1.f / red[0];
#pragma unroll
    for (int i = 0; i < 4; i++) AT[(size_t)(b * 1024 + tid + i * 256) * 16 + h] = v[i] * inv;
}

// P[(h*1024+d)*16+b] partial over s-half
__global__ void xctx(const float* __restrict__ enc, const float* __restrict__ AT,
                     float* __restrict__ P0, float* __restrict__ P1) {
    const int b = blockIdx.x, d = blockIdx.y * 256 + threadIdx.x, sz = blockIdx.z;
    const int s0 = sz * 512;
    float acc[16];
#pragma unroll
    for (int h = 0; h < 16; h++) acc[h] = 0.f;
    const float* ep = enc + (size_t)(b * 1024 + s0) * 1024 + d;
    const float4* ap = (const float4*)(AT + (size_t)(b * 1024 + s0) * 16);
    for (int s = 0; s < 512; s++) {
        float e = __ldg(ep); ep += 1024;
        float4 p0 = __ldg(ap), p1 = __ldg(ap + 1), p2 = __ldg(ap + 2), p3 = __ldg(ap + 3); ap += 4;
        acc[0] += e * p0.x; acc[1] += e * p0.y; acc[2] += e * p0.z; acc[3] += e * p0.w;
        acc[4] += e * p1.x; acc[5] += e * p1.y; acc[6] += e * p1.z; acc[7] += e * p1.w;
        acc[8] += e * p2.x; acc[9] += e * p2.y; acc[10] += e * p2.z; acc[11] += e * p2.w;
        acc[12] += e * p3.x; acc[13] += e * p3.y; acc[14] += e * p3.z; acc[15] += e * p3.w;
    }
    float* P = sz ? P1 : P0;
#pragma unroll
    for (int h = 0; h < 16; h++) P[(size_t)(h * 1024 + d) * 16 + b] = acc[h];
}

__global__ void logits_k(const float* __restrict__ XT, const float* __restrict__ W,
                         const float* __restrict__ bias, float* __restrict__ out) {
    const int v = blockIdx.x, tid = threadIdx.x;
    float acc[16];
#pragma unroll
    for (int b = 0; b < 16; b++) acc[b] = 0.f;
    for (int k = tid; k < 1024; k += 256) {
        float w = __ldg(&W[k * 20 + v]);
        const float4* a4 = (const float4*)(XT + k * 16);
        float4 a0 = a4[0], a1 = a4[1], a2 = a4[2], a3 = a4[3];
        acc[0] += w * a0.x; acc[1] += w * a0.y; acc[2] += w * a0.z; acc[3] += w * a0.w;
        acc[4] += w * a1.x; acc[5] += w * a1.y; acc[6] += w * a1.z; acc[7] += w * a1.w;
        acc[8] += w * a2.x; acc[9] += w * a2.y; acc[10] += w * a2.z; acc[11] += w * a2.w;
        acc[12] += w * a3.x; acc[13] += w * a3.y; acc[14] += w * a3.z; acc[15] += w * a3.w;
    }
    __shared__ float sh[256][17];
#pragma unroll
    for (int b = 0; b < 16; b++) sh[tid][b] = acc[b];
    __syncthreads();
    for (int st = 128; st > 0; st >>= 1) {
        if (tid < st)
#pragma unroll
            for (int b = 0; b < 16; b++) sh[tid][b] += sh[tid + st][b];
        __syncthreads();
    }
    if (tid < 16) out[tid * 20 + v] = sh[0][tid] + bias[v];
}

extern "C" void kernel_launch(void* const* d_in, const int* in_sizes, int n_in,
                              void* d_out, int out_size) {
    const float* x    = (const float*)d_in[0];
    const float* enc  = (const float*)d_in[1];
    const float* kc   = (const float*)d_in[2];
    const float* vc   = (const float*)d_in[3];
    const float* W[32]; for (int i = 4; i < 32; i++) W[i] = (const float*)d_in[i];
    void* bp; cudaGetSymbolAddress(&bp, g_buf);
    float* B = (float*)bp;
    float *XT = B + O_XT, *QT = B + O_QT, *KT = B + O_KT, *VT = B + O_VT;
    float *ATT = B + O_ATT, *TMP = B + O_TMP, *QC = B + O_QC, *CATT = B + O_CATT;
    float *HID = B + O_HID, *U = B + O_U, *SC = B + O_SC, *AT = B + O_AT;
    float *CT0 = B + O_CT0, *CT1 = B + O_CT1;

    tin<<<64, 256>>>(x, XT);
    for (int l = 0; l < 3; l++) {
        const size_t wo = (size_t)l * 1048576, bo = (size_t)l * 1024;
        const size_t co = (size_t)l * 16 * 16 * 1023 * 64;
        gemv16<<<64, 256>>>(XT, nullptr, W[4] + wo, W[5] + bo, nullptr, QT, 1024, 1024, 0, 0);
        gemv16<<<64, 256>>>(XT, nullptr, W[6] + wo, W[7] + bo, nullptr, KT, 1024, 1024, 0, 0);
        gemv16<<<64, 256>>>(XT, nullptr, W[8] + wo, W[9] + bo, nullptr, VT, 1024, 1024, 0, 0);
        self_attn<<<dim3(16, 16), 256>>>(QT, KT, VT, kc + co, vc + co, ATT);
        gemv16<<<64, 256>>>(ATT, nullptr, W[10] + wo, W[11] + bo, XT, TMP, 1024, 1024, 0, 0);
        lnk<<<16, 256>>>(TMP, W[24] + bo, W[25] + bo, XT);
        gemv16<<<64, 256>>>(XT, nullptr, W[12] + wo, W[13] + bo, nullptr, QC, 1024, 1024, 0, 0);
        ukern<<<1024, 256>>>(W[14] + wo, QC, U);
        xscores<<<dim3(16, 8), 128>>>(enc, U, SC);
        xsoftmax<<<dim3(16, 16), 256>>>(SC, AT);
        xctx<<<dim3(16, 4, 2), 256>>>(enc, AT, CT0, CT1);
        gemv16<<<64, 256>>>(CT0, CT1, W[16] + wo, W[17] + bo, nullptr, CATT, 1024, 1024, 1024, 0);
        gemv16<<<64, 256>>>(CATT, nullptr, W[18] + wo, W[19] + bo, XT, TMP, 1024, 1024, 0, 0);
        lnk<<<16, 256>>>(TMP, W[26] + bo, W[27] + bo, XT);
        gemv16<<<256, 256>>>(XT, nullptr, W[20] + (size_t)l * 4194304, W[21] + (size_t)l * 4096,
                             nullptr, HID, 4096, 1024, 0, 1);
        gemv16<<<64, 256>>>(HID, nullptr, W[22] + (size_t)l * 4194304, W[23] + bo, XT, TMP,
                            1024, 4096, 0, 0);
        lnk<<<16, 256>>>(TMP, W[28] + bo, W[29] + bo, XT);
    }
    logits_k<<<20, 256>>>(XT, W[30], W[31], (float*)d_out);
}

// round 13
// speedup vs baseline: 1.6055x; 1.6055x over previous
#include <cuda_runtime.h>
#include <math.h>

#define SCALE_F 0.125f
#define EPS_F 1e-5f

// scratch (float offsets)
#define O_XT   0
#define O_QT   16384
#define O_KT   32768
#define O_VT   49152
#define O_ATT  65536
#define O_TMP  81920
#define O_QC   98304
#define O_CATT 114688
#define O_HID  131072
#define O_U    196608
#define O_SC   458752
#define O_AT   720896
#define O_CT0  983040
#define O_CT1  1245184
#define O_P    1507328
__device__ float g_buf[1638400];

__global__ void tin(const float* __restrict__ x, float* __restrict__ XT) {
    int i = blockIdx.x * 256 + threadIdx.x;
    if (i < 16384) XT[(i & 1023) * 16 + (i >> 10)] = x[i];
}

// Stage 1: partial GEMV. grid (N/32, ksplit), 256 threads = 32 ox * 8 kw.
// P[gy*N*16 + o*16 + b] = sum over this block's k-range of A[(base+k)*16+b]*W[k*N+o]
__global__ void gemv_part(const float* __restrict__ A, const float* __restrict__ A2,
                          const float* __restrict__ W, float* __restrict__ P,
                          int N, int K, int ksplit, int hs) {
    __shared__ float as[8192];
    const int tid = threadIdx.x, ox = tid & 31, kw = tid >> 5;
    const int o = blockIdx.x * 32 + ox;
    const int klenB = K / ksplit;         // <= 512
    const int kl8 = klenB >> 3;
    const int kb0 = blockIdx.y * klenB;
    const int base = hs ? ((blockIdx.x * 32) >> 6) * hs : 0;

    const float* Ap = A + (size_t)(base + kb0) * 16;
    if (A2) {
        const float* Bp = A2 + (size_t)(base + kb0) * 16;
        for (int i = tid; i < klenB * 16; i += 256) as[i] = __ldg(Ap + i) + __ldg(Bp + i);
    } else {
        for (int i = tid; i < klenB * 16; i += 256) as[i] = __ldg(Ap + i);
    }
    __syncthreads();

    float acc[16];
#pragma unroll
    for (int b = 0; b < 16; b++) acc[b] = 0.f;
    const float* Wp = W + (size_t)(kb0 + kw * kl8) * N + o;
    const float* ap = &as[kw * kl8 * 16];
#pragma unroll 4
    for (int kk = 0; kk < kl8; kk++) {
        float w = __ldg(Wp); Wp += N;
        const float4* a4 = (const float4*)(ap + kk * 16);
        float4 a0 = a4[0], a1 = a4[1], a2 = a4[2], a3 = a4[3];
        acc[0] += w * a0.x; acc[1] += w * a0.y; acc[2] += w * a0.z; acc[3] += w * a0.w;
        acc[4] += w * a1.x; acc[5] += w * a1.y; acc[6] += w * a1.z; acc[7] += w * a1.w;
        acc[8] += w * a2.x; acc[9] += w * a2.y; acc[10] += w * a2.z; acc[11] += w * a2.w;
        acc[12] += w * a3.x; acc[13] += w * a3.y; acc[14] += w * a3.z; acc[15] += w * a3.w;
    }
    __syncthreads();
#pragma unroll
    for (int b = 0; b < 16; b++) as[kw * 544 + ox * 17 + b] = acc[b];
    __syncthreads();
    for (int p = tid; p < 512; p += 256) {
        const int ol = p >> 4, b = p & 15;
        float s = 0.f;
#pragma unroll
        for (int g = 0; g < 8; g++) s += as[g * 544 + ol * 17 + b];
        P[(size_t)blockIdx.y * N * 16 + (size_t)(blockIdx.x * 32 + ol) * 16 + b] = s;
    }
}

// Stage 2: sum ksplit partials + bias (+relu) (+resid)
__global__ void greduce(const float* __restrict__ P, const float* __restrict__ bias,
                        const float* __restrict__ resid, float* __restrict__ outT,
                        int N, int ksplit, int relu) {
    const int i = blockIdx.x * 256 + threadIdx.x;
    if (i >= N * 16) return;
    float s = 0.f;
    for (int g = 0; g < ksplit; g++) s += P[(size_t)g * N * 16 + i];
    float v = s + bias[i >> 4];
    if (relu) v = fmaxf(v, 0.f);
    if (resid) v += resid[i];
    outT[i] = v;
}

// one block per (b,h): scores over 1024 kv, softmax, weighted V sum
__global__ void self_attn(const float* __restrict__ QT, const float* __restrict__ KT,
                          const float* __restrict__ VT, const float* __restrict__ kc,
                          const float* __restrict__ vc, float* __restrict__ ATT) {
    const int b = blockIdx.x, h = blockIdx.y, tid = threadIdx.x;
    __shared__ float q[64], sc[1024], red[256], outp[4][64];
    if (tid < 64) q[tid] = QT[(h * 64 + tid) * 16 + b];
    __syncthreads();
    const size_t cbase = (size_t)(b * 16 + h) * 1023 * 64;
    for (int t = tid; t < 1024; t += 256) {
        float a = 0.f;
        if (t < 1023) {
            const float4* kp = (const float4*)(kc + cbase + (size_t)t * 64);
            const float4* qp = (const float4*)q;
#pragma unroll
            for (int i = 0; i < 16; i++) {
                float4 kv = __ldg(kp + i), qv = qp[i];
                a += kv.x * qv.x + kv.y * qv.y + kv.z * qv.z + kv.w * qv.w;
            }
        } else {
            for (int j = 0; j < 64; j++) a += q[j] * KT[(h * 64 + j) * 16 + b];
        }
        sc[t] = a * SCALE_F;
    }
    __syncthreads();
    float m = -1e30f;
    for (int t = tid; t < 1024; t += 256) m = fmaxf(m, sc[t]);
    red[tid] = m; __syncthreads();
    for (int s = 128; s > 0; s >>= 1) { if (tid < s) red[tid] = fmaxf(red[tid], red[tid + s]); __syncthreads(); }
    m = red[0]; __syncthreads();
    float ssum = 0.f;
    for (int t = tid; t < 1024; t += 256) { float e = __expf(sc[t] - m); sc[t] = e; ssum += e; }
    red[tid] = ssum; __syncthreads();
    for (int s = 128; s > 0; s >>= 1) { if (tid < s) red[tid] += red[tid + s]; __syncthreads(); }
    const float sum = red[0];
    __syncthreads();
    const int g = tid >> 6, j = tid & 63;
    float acc = 0.f;
#pragma unroll 8
    for (int kk = 0; kk < 255; kk++) {       // t = g + 4*kk <= 3+1016 < 1023: always cache
        const int t = g + 4 * kk;
        acc += sc[t] * __ldg(vc + cbase + (size_t)t * 64 + j);
    }
    {
        const int t = g + 1020;              // tail: only g==3 hits t==1023
        float v = (t < 1023) ? __ldg(vc + cbase + (size_t)t * 64 + j) : VT[(h * 64 + j) * 16 + b];
        acc += sc[t] * v;
    }
    outp[g][j] = acc;
    __syncthreads();
    if (tid < 64)
        ATT[(h * 64 + tid) * 16 + b] = (outp[0][tid] + outp[1][tid] + outp[2][tid] + outp[3][tid]) / sum;
}

__global__ void lnk(const float* __restrict__ T, const float* __restrict__ g,
                    const float* __restrict__ be, float* __restrict__ XT) {
    const int b = blockIdx.x, tid = threadIdx.x;
    __shared__ float red[256];
    float s = 0.f;
    for (int o = tid; o < 1024; o += 256) s += T[o * 16 + b];
    red[tid] = s; __syncthreads();
    for (int st = 128; st > 0; st >>= 1) { if (tid < st) red[tid] += red[tid + st]; __syncthreads(); }
    const float mean = red[0] * (1.f / 1024.f);
    __syncthreads();
    float v = 0.f;
    for (int o = tid; o < 1024; o += 256) { float d = T[o * 16 + b] - mean; v += d * d; }
    red[tid] = v; __syncthreads();
    for (int st = 128; st > 0; st >>= 1) { if (tid < st) red[tid] += red[tid + st]; __syncthreads(); }
    const float rstd = rsqrtf(red[0] * (1.f / 1024.f) + EPS_F);
    for (int o = tid; o < 1024; o += 256)
        XT[o * 16 + b] = (T[o * 16 + b] - mean) * rstd * g[o] + be[o];
}

// U[(b*16+h)*1024+d] = sum_j Wk[d*1024 + h*64+j] * QC[(h*64+j)*16+b]
__global__ void ukern(const float* __restrict__ Wk, const float* __restrict__ QC,
                      float* __restrict__ U) {
    const int d = blockIdx.x, tid = threadIdx.x;
    __shared__ float w[1024];
    for (int i = tid; i < 1024; i += 256) w[i] = __ldg(&Wk[(size_t)d * 1024 + i]);
    __syncthreads();
    const int b = tid & 15, h = tid >> 4;
    float a = 0.f;
#pragma unroll 8
    for (int j = 0; j < 64; j++) a += w[h * 64 + j] * QC[(h * 64 + j) * 16 + b];
    U[(size_t)(b * 16 + h) * 1024 + d] = a;
}

// SC[(b*16+h)*1024+s] = enc[b,s,:] . U[b,h,:]
__global__ void xscores(const float* __restrict__ enc, const float* __restrict__ U,
                        float* __restrict__ SC) {
    const int b = blockIdx.x, s = blockIdx.y * 128 + threadIdx.x;
    __shared__ float ush[16][512];
    float acc[16];
#pragma unroll
    for (int h = 0; h < 16; h++) acc[h] = 0.f;
    const float* ep = enc + (size_t)(b * 1024 + s) * 1024;
    for (int half = 0; half < 2; half++) {
        __syncthreads();
        for (int i = threadIdx.x; i < 8192; i += 128)
            ush[i >> 9][i & 511] = __ldg(&U[(size_t)(b * 16 + (i >> 9)) * 1024 + half * 512 + (i & 511)]);
        __syncthreads();
        for (int d = 0; d < 512; d += 4) {
            float4 e = __ldg((const float4*)(ep + half * 512 + d));
#pragma unroll
            for (int h = 0; h < 16; h++) {
                float4 u4 = *(const float4*)&ush[h][d];
                acc[h] += e.x * u4.x + e.y * u4.y + e.z * u4.z + e.w * u4.w;
            }
        }
    }
#pragma unroll
    for (int h = 0; h < 16; h++) SC[(size_t)(b * 16 + h) * 1024 + s] = acc[h];
}

__global__ void xsoftmax(const float* __restrict__ SC, float* __restrict__ AT) {
    const int b = blockIdx.x, h = blockIdx.y, tid = threadIdx.x;
    const float* p = SC + (size_t)(b * 16 + h) * 1024;
    __shared__ float red[256];
    float v[4], m = -1e30f;
#pragma unroll
    for (int i = 0; i < 4; i++) { v[i] = SCALE_F * p[tid + i * 256]; m = fmaxf(m, v[i]); }
    red[tid] = m; __syncthreads();
    for (int st = 128; st > 0; st >>= 1) { if (tid < st) red[tid] = fmaxf(red[tid], red[tid + st]); __syncthreads(); }
    m = red[0]; __syncthreads();
    float ssum = 0.f;
#pragma unroll
    for (int i = 0; i < 4; i++) { v[i] = __expf(v[i] - m); ssum += v[i]; }
    red[tid] = ssum; __syncthreads();
    for (int st = 128; st > 0; st >>= 1) { if (tid < st) red[tid] += red[tid + st]; __syncthreads(); }
    const float inv = 1.f / red[0];
#pragma unroll
    for (int i = 0; i < 4; i++) AT[(size_t)(b * 1024 + tid + i * 256) * 16 + h] = v[i] * inv;
}

// P[(h*1024+d)*16+b] partial over s-half
__global__ void xctx(const float* __restrict__ enc, const float* __restrict__ AT,
                     float* __restrict__ P0, float* __restrict__ P1) {
    const int b = blockIdx.x, d = blockIdx.y * 256 + threadIdx.x, sz = blockIdx.z;
    const int s0 = sz * 512;
    float acc[16];
#pragma unroll
    for (int h = 0; h < 16; h++) acc[h] = 0.f;
    const float* ep = enc + (size_t)(b * 1024 + s0) * 1024 + d;
    const float4* ap = (const float4*)(AT + (size_t)(b * 1024 + s0) * 16);
#pragma unroll 4
    for (int s = 0; s < 512; s++) {
        float e = __ldg(ep); ep += 1024;
        float4 p0 = __ldg(ap), p1 = __ldg(ap + 1), p2 = __ldg(ap + 2), p3 = __ldg(ap + 3); ap += 4;
        acc[0] += e * p0.x; acc[1] += e * p0.y; acc[2] += e * p0.z; acc[3] += e * p0.w;
        acc[4] += e * p1.x; acc[5] += e * p1.y; acc[6] += e * p1.z; acc[7] += e * p1.w;
        acc[8] += e * p2.x; acc[9] += e * p2.y; acc[10] += e * p2.z; acc[11] += e * p2.w;
        acc[12] += e * p3.x; acc[13] += e * p3.y; acc[14] += e * p3.z; acc[15] += e * p3.w;
    }
    float* P = sz ? P1 : P0;
#pragma unroll
    for (int h = 0; h < 16; h++) P[(size_t)(h * 1024 + d) * 16 + b] = acc[h];
}

__global__ void logits_k(const float* __restrict__ XT, const float* __restrict__ W,
                         const float* __restrict__ bias, float* __restrict__ out) {
    const int v = blockIdx.x, tid = threadIdx.x;
    float acc[16];
#pragma unroll
    for (int b = 0; b < 16; b++) acc[b] = 0.f;
    for (int k = tid; k < 1024; k += 256) {
        float w = __ldg(&W[k * 20 + v]);
        const float4* a4 = (const float4*)(XT + k * 16);
        float4 a0 = a4[0], a1 = a4[1], a2 = a4[2], a3 = a4[3];
        acc[0] += w * a0.x; acc[1] += w * a0.y; acc[2] += w * a0.z; acc[3] += w * a0.w;
        acc[4] += w * a1.x; acc[5] += w * a1.y; acc[6] += w * a1.z; acc[7] += w * a1.w;
        acc[8] += w * a2.x; acc[9] += w * a2.y; acc[10] += w * a2.z; acc[11] += w * a2.w;
        acc[12] += w * a3.x; acc[13] += w * a3.y; acc[14] += w * a3.z; acc[15] += w * a3.w;
    }
    __shared__ float sh[256][17];
#pragma unroll
    for (int b = 0; b < 16; b++) sh[tid][b] = acc[b];
    __syncthreads();
    for (int st = 128; st > 0; st >>= 1) {
        if (tid < st)
#pragma unroll
            for (int b = 0; b < 16; b++) sh[tid][b] += sh[tid + st][b];
        __syncthreads();
    }
    if (tid < 16) out[tid * 20 + v] = sh[0][tid] + bias[v];
}

static inline void gemv(const float* A, const float* A2, const float* W,
                        const float* bias, const float* resid, float* P,
                        float* outT, int N, int K, int ksplit, int hs, int relu) {
    gemv_part<<<dim3(N / 32, ksplit), 256>>>(A, A2, W, P, N, K, ksplit, hs);
    greduce<<<N * 16 / 256, 256>>>(P, bias, resid, outT, N, ksplit, relu);
}

extern "C" void kernel_launch(void* const* d_in, const int* in_sizes, int n_in,
                              void* d_out, int out_size) {
    const float* x    = (const float*)d_in[0];
    const float* enc  = (const float*)d_in[1];
    const float* kc   = (const float*)d_in[2];
    const float* vc   = (const float*)d_in[3];
    const float* W[32]; for (int i = 4; i < 32; i++) W[i] = (const float*)d_in[i];
    void* bp; cudaGetSymbolAddress(&bp, g_buf);
    float* B = (float*)bp;
    float *XT = B + O_XT, *QT = B + O_QT, *KT = B + O_KT, *VT = B + O_VT;
    float *ATT = B + O_ATT, *TMP = B + O_TMP, *QC = B + O_QC, *CATT = B + O_CATT;
    float *HID = B + O_HID, *U = B + O_U, *SC = B + O_SC, *AT = B + O_AT;
    float *CT0 = B + O_CT0, *CT1 = B + O_CT1, *P = B + O_P;

    tin<<<64, 256>>>(x, XT);
    for (int l = 0; l < 3; l++) {
        const size_t wo = (size_t)l * 1048576, bo = (size_t)l * 1024;
        const size_t co = (size_t)l * 16 * 16 * 1023 * 64;
        gemv(XT, nullptr, W[4] + wo, W[5] + bo, nullptr, P, QT, 1024, 1024, 8, 0, 0);
        gemv(XT, nullptr, W[6] + wo, W[7] + bo, nullptr, P, KT, 1024, 1024, 8, 0, 0);
        gemv(XT, nullptr, W[8] + wo, W[9] + bo, nullptr, P, VT, 1024, 1024, 8, 0, 0);
        self_attn<<<dim3(16, 16), 256>>>(QT, KT, VT, kc + co, vc + co, ATT);
        gemv(ATT, nullptr, W[10] + wo, W[11] + bo, XT, P, TMP, 1024, 1024, 8, 0, 0);
        lnk<<<16, 256>>>(TMP, W[24] + bo, W[25] + bo, XT);
        gemv(XT, nullptr, W[12] + wo, W[13] + bo, nullptr, P, QC, 1024, 1024, 8, 0, 0);
        ukern<<<1024, 256>>>(W[14] + wo, QC, U);
        xscores<<<dim3(16, 8), 128>>>(enc, U, SC);
        xsoftmax<<<dim3(16, 16), 256>>>(SC, AT);
        xctx<<<dim3(16, 4, 2), 256>>>(enc, AT, CT0, CT1);
        gemv(CT0, CT1, W[16] + wo, W[17] + bo, nullptr, P, CATT, 1024, 1024, 8, 1024, 0);
        gemv(CATT, nullptr, W[18] + wo, W[19] + bo, XT, P, TMP, 1024, 1024, 8, 0, 0);
        lnk<<<16, 256>>>(TMP, W[26] + bo, W[27] + bo, XT);
        gemv(XT, nullptr, W[20] + (size_t)l * 4194304, W[21] + (size_t)l * 4096,
             nullptr, P, HID, 4096, 1024, 2, 0, 1);
        gemv(HID, nullptr, W[22] + (size_t)l * 4194304, W[23] + bo, XT, P, TMP,
             1024, 4096, 8, 0, 0);
        lnk<<<16, 256>>>(TMP, W[28] + bo, W[29] + bo, XT);
    }
    logits_k<<<20, 256>>>(XT, W[30], W[31], (float*)d_out);
}